// round 5
// baseline (speedup 1.0000x reference)
#include <cuda_runtime.h>
#include <math.h>

namespace {
constexpr int B_   = 32;
constexpr int S_   = 1024;
constexpr int D_   = 512;
constexpr int H_   = 4;
constexpr int DH_  = 384;
constexpr int FFN_ = 2048;
constexpr int NCH_ = 8;     // 128-row chunks for alpha/y
constexpr int NB_  = 296;   // two blocks per SM — all resident
constexpr int NT_  = 512;
}

// ---------------- static scratch ----------------
__device__ float g_Pos[S_ * D_];                  // 2 MB
__device__ float g_x0[B_ * D_];
__device__ float g_q0p[8][B_ * D_];               // q0 partials
__device__ float g_w[B_ * H_ * D_];
__device__ float g_c[B_ * H_];
__device__ float g_ypart[B_ * NCH_ * H_ * D_];    // 2 MB
__device__ float g_Apart[B_ * NCH_ * H_];
__device__ float g_hp[8][B_ * D_];                // F1 partials
__device__ float g_x1p[8][B_ * D_];               // F2 partials
__device__ float g_x1n[B_ * D_];                  // post-LN1
__device__ float g_h1p[8][B_ * FFN_];             // F3 partials
__device__ float g_x2p[32][B_ * D_];              // F4 partials
__device__ float g_x2[B_ * D_];                   // post-LN2
__device__ float g_hidp[8][B_ * D_];              // F5 partials

// ---------------- grid barrier ----------------
__device__ unsigned g_cnt = 0;
__device__ volatile unsigned g_gen = 0;

__device__ __forceinline__ void grid_bar() {
    __syncthreads();
    if (threadIdx.x == 0) {
        unsigned gen = g_gen;               // read BEFORE arriving
        __threadfence();                    // release
        if (atomicAdd(&g_cnt, 1u) == NB_ - 1u) {
            g_cnt = 0;
            __threadfence();
            g_gen = gen + 1u;
        } else {
            while (g_gen == gen) __nanosleep(64);
        }
        __threadfence();                    // acquire
    }
    __syncthreads();
}

// ---------------- shared memory union ----------------
struct SA { float xs[16][512]; float ws[2048]; float al[128][4]; float cs[4]; };
struct SG { float As[32][64]; };
struct SW { float As[32][128]; };
struct SR { float red[512]; };

__device__ __forceinline__ float redsum(float v, float* red) {
    int tid = threadIdx.x;
    red[tid] = v;
    __syncthreads();
#pragma unroll
    for (int s = 256; s > 0; s >>= 1) {
        if (tid < s) red[tid] += red[tid + s];
        __syncthreads();
    }
    float r = red[0];
    __syncthreads();
    return r;
}

// Batched skinny GEMM stage: C[32, NCT*128] += A[32, NKT*64] @ W
#define GEMM_BODY(NCT, NKT, STAGE_EXPR, INIT_STMT, WADDR_EXPR, OUT_STMT)        \
  for (int tt = blk; tt < (NCT) * (NKT); tt += NB_) {                           \
    const int ct = tt / (NKT), kb = tt % (NKT);                                 \
    const int col = ct * 128 + cg * 4;  (void)col;                              \
    _Pragma("unroll")                                                           \
    for (int r = 0; r < 4; r++) {                                               \
      int idx = tid + NT_ * r;                                                  \
      int bb = idx >> 6, kk = idx & 63;                                         \
      int kg = kb * 64 + kk;  (void)kg;                                         \
      sm.g.As[bb][kk] = (STAGE_EXPR);                                           \
    }                                                                           \
    __syncthreads();                                                            \
    float4 acc[2];                                                              \
    INIT_STMT;                                                                  \
    _Pragma("unroll 8")                                                         \
    for (int k = 0; k < 64; k++) {                                              \
      int kg = kb * 64 + k;                                                     \
      float4 wv = *(const float4*)(WADDR_EXPR);                                 \
      _Pragma("unroll")                                                         \
      for (int j = 0; j < 2; j++) {                                             \
        float a = sm.g.As[bg * 2 + j][k];                                       \
        acc[j].x += a * wv.x; acc[j].y += a * wv.y;                             \
        acc[j].z += a * wv.z; acc[j].w += a * wv.w;                             \
      }                                                                         \
    }                                                                           \
    OUT_STMT;                                                                   \
    __syncthreads();                                                            \
  }

#define ACC_ZERO() do {                                                         \
    acc[0] = make_float4(0.f, 0.f, 0.f, 0.f);                                   \
    acc[1] = make_float4(0.f, 0.f, 0.f, 0.f); } while (0)

__global__ __launch_bounds__(NT_, 2) void mega_kernel(
    const int*   __restrict__ tok,  const float* __restrict__ emb,
    const float* __restrict__ Wp,   const float* __restrict__ bp,
    const float* __restrict__ Wo,   const float* __restrict__ bo,
    const float* __restrict__ g1,   const float* __restrict__ bln1,
    const float* __restrict__ W1,   const float* __restrict__ b1,
    const float* __restrict__ W2,   const float* __restrict__ b2,
    const float* __restrict__ g2,   const float* __restrict__ bln2,
    const float* __restrict__ Wh,   const float* __restrict__ bhw,
    const float* __restrict__ Wf,   const float* __restrict__ bf,
    float* __restrict__ out, int out_size)
{
    __shared__ union { SA a; SG g; SW w; SR r; } sm;
    const int blk = blockIdx.x;
    const int tid = threadIdx.x;
    const int lane = tid & 31, wid = tid >> 5;
    const int cg = lane, bg = wid;

    // ========== Stage 1: q0 GEMM (blk<32)  ||  pos table (blk>=32) ==========
    // pos row 0 is [0,1,0,1,...] so x0 = emb[t0] + (d odd ? 1 : 0) — no table dep.
    if (blk < 32) {
        GEMM_BODY(4, 8,
            /*stage*/ ({
                float v = emb[(size_t)tok[bb * S_] * D_ + kg] + (float)(kg & 1);
                if (ct == 0) g_x0[bb * D_ + kg] = v;
                v; }),
            /*init*/ do {
                if (kb == 0) {
                    float4 bv = *(const float4*)&bp[ct * DH_ + cg * 4];
                    acc[0] = bv; acc[1] = bv;
                } else ACC_ZERO();
            } while (0),
            /*W*/ (Wp + ((size_t)ct * D_ + kg) * DH_ + cg * 4),
            /*out*/ do {
                _Pragma("unroll")
                for (int j = 0; j < 2; j++)
                    *(float4*)&g_q0p[kb][(bg * 2 + j) * D_ + col] = acc[j];
            } while (0));
    } else {
        for (int idx = (blk - 32) * NT_ + tid; idx < S_ * D_; idx += 264 * NT_) {
            int t = idx >> 9;
            int i = idx & 511;
            float expn = (float)(2 * (i >> 1)) * (1.0f / (float)D_);
            float ang  = (float)t / powf(10000.0f, expn);
            g_Pos[idx] = (i & 1) ? cosf(ang) : sinf(ang);
        }
    }
    grid_bar();

    // ========== Stage 2: w = Wk q0 (blk<16)  +  c (blk 16..47) ==========
    if (blk < 16) {
        const int ct = blk;
        const int h = ct >> 2;
        const int d0 = (ct & 3) * 128 + cg * 4;
        // stage q0 slice [32 batches][128 e] (sum 8 partials)
#pragma unroll
        for (int r = 0; r < 8; r++) {
            int idx = tid + NT_ * r;          // 0..4095
            int bb = idx >> 7, kk = idx & 127;
            float s = 0.f;
#pragma unroll
            for (int p = 0; p < 8; p++) s += g_q0p[p][bb * D_ + h * 128 + kk];
            sm.w.As[bb][kk] = s;
        }
        __syncthreads();
        float acc[2][4] = {};
#pragma unroll 4
        for (int k4 = 0; k4 < 32; k4++) {
            float4 wv[4];
#pragma unroll
            for (int j = 0; j < 4; j++)
                wv[j] = *(const float4*)&Wp[((size_t)h * D_ + d0 + j) * DH_ + 128 + k4 * 4];
#pragma unroll
            for (int jb = 0; jb < 2; jb++) {
                const float* Ab = sm.w.As[bg * 2 + jb] + k4 * 4;
                float a0 = Ab[0], a1 = Ab[1], a2 = Ab[2], a3 = Ab[3];
#pragma unroll
                for (int j = 0; j < 4; j++)
                    acc[jb][j] += wv[j].x * a0 + wv[j].y * a1 + wv[j].z * a2 + wv[j].w * a3;
            }
        }
#pragma unroll
        for (int jb = 0; jb < 2; jb++) {
            int b = bg * 2 + jb;
#pragma unroll
            for (int j = 0; j < 4; j++)
                g_w[b * (H_ * D_) + h * D_ + d0 + j] = acc[jb][j];
        }
        __syncthreads();
    } else if (blk < 48) {
        int b = blk - 16;
        int h = tid >> 7, e = tid & 127;
        float q = 0.f;
#pragma unroll
        for (int p = 0; p < 8; p++) q += g_q0p[p][b * D_ + tid];
        sm.r.red[tid] = q * bp[h * DH_ + 128 + e];
        __syncthreads();
#pragma unroll
        for (int s = 64; s > 0; s >>= 1) {
            if ((tid & 127) < s) sm.r.red[tid] += sm.r.red[tid + s];
            __syncthreads();
        }
        if ((tid & 127) == 0) g_c[b * H_ + h] = sm.r.red[tid];
        __syncthreads();
    }
    grid_bar();

    // ========== Stage 3: fused gather + alpha + y (256 tiles, 1 wave) ==========
    for (int t = blk; t < B_ * NCH_; t += NB_) {
        int b = t & 31, chunk = t >> 5;
        const float4* ws4  = (const float4*)sm.a.ws;
        const float4* emb4 = (const float4*)emb;
        const float4* pos4 = (const float4*)g_Pos;
        float4* xs4 = (float4*)sm.a.xs;

#pragma unroll
        for (int r = 0; r < 4; r++)
            sm.a.ws[tid + NT_ * r] = g_w[b * (H_ * D_) + tid + NT_ * r];
        if (tid < H_) sm.a.cs[tid] = g_c[b * H_ + tid];
        __syncthreads();

        float y0 = 0.f, y1 = 0.f, y2 = 0.f, y3 = 0.f;

        for (int sub = 0; sub < 8; sub++) {
            int r0 = chunk * 128 + sub * 16;
#pragma unroll
            for (int r = 0; r < 4; r++) {
                int idx = tid + NT_ * r;
                int row = idx >> 7, c4 = idx & 127;
                int tk  = tok[b * S_ + r0 + row];
                float4 e = emb4[(size_t)tk * 128 + c4];
                float4 p = pos4[(size_t)(r0 + row) * 128 + c4];
                float4 vv;
                vv.x = e.x + p.x; vv.y = e.y + p.y; vv.z = e.z + p.z; vv.w = e.w + p.w;
                xs4[row * 128 + c4] = vv;
            }
            __syncthreads();

            {   // alpha: 16 warps, one row each
                const float4* xr = (const float4*)&sm.a.xs[wid][0];
                float s0 = 0.f, s1 = 0.f, s2 = 0.f, s3 = 0.f;
#pragma unroll
                for (int k = 0; k < 4; k++) {
                    int f4 = lane + 32 * k;
                    float4 xv = xr[f4];
                    float4 w0 = ws4[0 * 128 + f4];
                    float4 w1 = ws4[1 * 128 + f4];
                    float4 w2 = ws4[2 * 128 + f4];
                    float4 w3 = ws4[3 * 128 + f4];
                    s0 += xv.x * w0.x + xv.y * w0.y + xv.z * w0.z + xv.w * w0.w;
                    s1 += xv.x * w1.x + xv.y * w1.y + xv.z * w1.z + xv.w * w1.w;
                    s2 += xv.x * w2.x + xv.y * w2.y + xv.z * w2.z + xv.w * w2.w;
                    s3 += xv.x * w3.x + xv.y * w3.y + xv.z * w3.z + xv.w * w3.w;
                }
#pragma unroll
                for (int off = 16; off > 0; off >>= 1) {
                    s0 += __shfl_xor_sync(0xffffffff, s0, off);
                    s1 += __shfl_xor_sync(0xffffffff, s1, off);
                    s2 += __shfl_xor_sync(0xffffffff, s2, off);
                    s3 += __shfl_xor_sync(0xffffffff, s3, off);
                }
                if (lane == 0) {
                    sm.a.al[sub * 16 + wid][0] = s0 + sm.a.cs[0];
                    sm.a.al[sub * 16 + wid][1] = s1 + sm.a.cs[1];
                    sm.a.al[sub * 16 + wid][2] = s2 + sm.a.cs[2];
                    sm.a.al[sub * 16 + wid][3] = s3 + sm.a.cs[3];
                }
            }
            __syncthreads();

#pragma unroll
            for (int tt = 0; tt < 16; tt++) {
                float xv = sm.a.xs[tt][tid];
                int ta = sub * 16 + tt;
                y0 += sm.a.al[ta][0] * xv;
                y1 += sm.a.al[ta][1] * xv;
                y2 += sm.a.al[ta][2] * xv;
                y3 += sm.a.al[ta][3] * xv;
            }
            __syncthreads();
        }

        float* yp = g_ypart + ((size_t)(b * NCH_ + chunk)) * (H_ * D_);
        yp[0 * D_ + tid] = y0;
        yp[1 * D_ + tid] = y1;
        yp[2 * D_ + tid] = y2;
        yp[3 * D_ + tid] = y3;
        if (tid < H_) {
            float a = 0.f;
#pragma unroll 8
            for (int r = 0; r < 128; r++) a += sm.a.al[r][tid];
            g_Apart[(b * NCH_ + chunk) * H_ + tid] = a;
        }
        __syncthreads();
    }
    grid_bar();

    // ========== F1: heads = y @ Wv + A*bv ==========
    {
        GEMM_BODY(4, 8,
            /*stage*/ ({
                float s = 0.f;
                _Pragma("unroll")
                for (int c = 0; c < NCH_; c++)
                    s += g_ypart[((size_t)(bb * NCH_ + c)) * (H_ * D_) + ct * D_ + kg];
                s; }),
            /*init*/ do {
                if (kb == 0) {
                    float4 bv = *(const float4*)&bp[ct * DH_ + 256 + cg * 4];
                    _Pragma("unroll")
                    for (int j = 0; j < 2; j++) {
                        int bj = bg * 2 + j;
                        float av = 0.f;
                        _Pragma("unroll")
                        for (int c = 0; c < NCH_; c++) av += g_Apart[(bj * NCH_ + c) * H_ + ct];
                        acc[j].x = av * bv.x; acc[j].y = av * bv.y;
                        acc[j].z = av * bv.z; acc[j].w = av * bv.w;
                    }
                } else ACC_ZERO();
            } while (0),
            /*W*/ (Wp + ((size_t)ct * D_ + kg) * DH_ + 256 + cg * 4),
            /*out*/ do {
                _Pragma("unroll")
                for (int j = 0; j < 2; j++)
                    *(float4*)&g_hp[kb][(bg * 2 + j) * D_ + col] = acc[j];
            } while (0));
    }
    grid_bar();

    // ========== F2: x1 = scale*heads @ Wo + bo + x0 ==========
    {
        GEMM_BODY(4, 8,
            /*stage*/ ({
                float s = 0.f;
                _Pragma("unroll")
                for (int p = 0; p < 8; p++) s += g_hp[p][bb * D_ + kg];
                s * 0.03125f; }),
            /*init*/ do {
                if (kb == 0) {
                    float4 bv = *(const float4*)&bo[col];
                    _Pragma("unroll")
                    for (int j = 0; j < 2; j++) {
                        float4 xv = *(const float4*)&g_x0[(bg * 2 + j) * D_ + col];
                        acc[j].x = bv.x + xv.x; acc[j].y = bv.y + xv.y;
                        acc[j].z = bv.z + xv.z; acc[j].w = bv.w + xv.w;
                    }
                } else ACC_ZERO();
            } while (0),
            /*W*/ (Wo + (size_t)kg * D_ + col),
            /*out*/ do {
                _Pragma("unroll")
                for (int j = 0; j < 2; j++)
                    *(float4*)&g_x1p[kb][(bg * 2 + j) * D_ + col] = acc[j];
            } while (0));
    }
    grid_bar();

    // ========== LN1 ==========
    if (blk < B_) {
        int b = blk;
        float v = 0.f;
#pragma unroll
        for (int p = 0; p < 8; p++) v += g_x1p[p][b * D_ + tid];
        float mu  = redsum(v, sm.r.red) * (1.f / D_);
        float dv  = v - mu;
        float var = redsum(dv * dv, sm.r.red) * (1.f / D_);
        g_x1n[b * D_ + tid] = dv * rsqrtf(var + 1e-3f) * g1[tid] + bln1[tid];
    }
    grid_bar();

    // ========== F3: h1 = x1n @ W1 + b1 ==========
    {
        GEMM_BODY(16, 8,
            /*stage*/ (g_x1n[bb * D_ + kg]),
            /*init*/ do {
                if (kb == 0) {
                    float4 bv = *(const float4*)&b1[col];
                    acc[0] = bv; acc[1] = bv;
                } else ACC_ZERO();
            } while (0),
            /*W*/ (W1 + (size_t)kg * FFN_ + col),
            /*out*/ do {
                _Pragma("unroll")
                for (int j = 0; j < 2; j++)
                    *(float4*)&g_h1p[kb][(bg * 2 + j) * FFN_ + col] = acc[j];
            } while (0));
    }
    grid_bar();

    // ========== F4: x2 = relu(h1) @ W2 + b2 + x1n ==========
    {
        GEMM_BODY(4, 32,
            /*stage*/ ({
                float s = 0.f;
                _Pragma("unroll")
                for (int p = 0; p < 8; p++) s += g_h1p[p][bb * FFN_ + kg];
                fmaxf(s, 0.f); }),
            /*init*/ do {
                if (kb == 0) {
                    float4 bv = *(const float4*)&b2[col];
                    _Pragma("unroll")
                    for (int j = 0; j < 2; j++) {
                        float4 xv = *(const float4*)&g_x1n[(bg * 2 + j) * D_ + col];
                        acc[j].x = bv.x + xv.x; acc[j].y = bv.y + xv.y;
                        acc[j].z = bv.z + xv.z; acc[j].w = bv.w + xv.w;
                    }
                } else ACC_ZERO();
            } while (0),
            /*W*/ (W2 + (size_t)kg * D_ + col),
            /*out*/ do {
                _Pragma("unroll")
                for (int j = 0; j < 2; j++)
                    *(float4*)&g_x2p[kb][(bg * 2 + j) * D_ + col] = acc[j];
            } while (0));
    }
    grid_bar();

    // ========== LN2 ==========
    if (blk < B_) {
        int b = blk;
        float v = 0.f;
#pragma unroll
        for (int p = 0; p < 32; p++) v += g_x2p[p][b * D_ + tid];
        float mu  = redsum(v, sm.r.red) * (1.f / D_);
        float dv  = v - mu;
        float var = redsum(dv * dv, sm.r.red) * (1.f / D_);
        g_x2[b * D_ + tid] = dv * rsqrtf(var + 1e-3f) * g2[tid] + bln2[tid];
    }
    grid_bar();

    // ========== F5: hid = x2 @ Wh + bh ==========
    {
        GEMM_BODY(4, 8,
            /*stage*/ (g_x2[bb * D_ + kg]),
            /*init*/ do {
                if (kb == 0) {
                    float4 bv = *(const float4*)&bhw[col];
                    acc[0] = bv; acc[1] = bv;
                } else ACC_ZERO();
            } while (0),
            /*W*/ (Wh + (size_t)kg * D_ + col),
            /*out*/ do {
                _Pragma("unroll")
                for (int j = 0; j < 2; j++)
                    *(float4*)&g_hidp[kb][(bg * 2 + j) * D_ + col] = acc[j];
            } while (0));
    }
    grid_bar();

    // ========== logits ==========
    if (blk < B_) {
        int b = blk;
        float v = 0.f;
#pragma unroll
        for (int p = 0; p < 8; p++) v += g_hidp[p][b * D_ + tid];
        float hid = fmaxf(v, 0.f);
        float s = redsum(hid * Wf[tid], sm.r.red);
        if (tid == 0) {
            float logit = s + bf[0];
            if (b < out_size)      out[b]      = logit;
            if (B_ + b < out_size) out[B_ + b] = 1.f / (1.f + expf(-logit));
        }
    }
}

// ---------------------------------------------------------------------------
extern "C" void kernel_launch(void* const* d_in, const int* in_sizes, int n_in,
                              void* d_out, int out_size) {
    const int*   inputs = (const int*)  d_in[0];
    const float* emb    = (const float*)d_in[1];
    const float* Wp     = (const float*)d_in[2];
    const float* bp     = (const float*)d_in[3];
    const float* Wo     = (const float*)d_in[4];
    const float* bo     = (const float*)d_in[5];
    const float* ln1g   = (const float*)d_in[6];
    const float* ln1b   = (const float*)d_in[7];
    const float* W1     = (const float*)d_in[8];
    const float* b1     = (const float*)d_in[9];
    const float* W2     = (const float*)d_in[10];
    const float* b2     = (const float*)d_in[11];
    const float* ln2g   = (const float*)d_in[12];
    const float* ln2b   = (const float*)d_in[13];
    const float* Wh     = (const float*)d_in[14];
    const float* bhp    = (const float*)d_in[15];
    const float* Wf     = (const float*)d_in[16];
    const float* bf     = (const float*)d_in[17];
    float* out = (float*)d_out;

    mega_kernel<<<NB_, NT_>>>(inputs, emb, Wp, bp, Wo, bo, ln1g, ln1b,
                              W1, b1, W2, b2, ln2g, ln2b, Wh, bhp, Wf, bf,
                              out, out_size);
}